// round 15
// baseline (speedup 1.0000x reference)
#include <cuda_runtime.h>
#include <cuda_fp16.h>
#include <cstdint>

// Problem constants
#define BATCH   2
#define S_LEN   4096
#define DMODEL  512
#define NHEAD   8
#define DHEAD   64
#define WNBR    32
#define M_TOT   (BATCH * S_LEN)      // 8192

// ---------------------------------------------------------------------------
// PTX helpers — base sm_103 only (NO tcgen05)
// ---------------------------------------------------------------------------
__device__ __forceinline__ uint32_t smem_to_u32(const void* p) {
    uint32_t a;
    asm("{ .reg .u64 t; cvta.to.shared.u64 t, %1; cvt.u32.u64 %0, t; }" : "=r"(a) : "l"(p));
    return a;
}
__device__ __forceinline__ void ldsm_x4(uint32_t* r, uint32_t addr) {
    asm volatile("ldmatrix.sync.aligned.m8n8.x4.shared.b16 {%0,%1,%2,%3}, [%4];"
                 : "=r"(r[0]), "=r"(r[1]), "=r"(r[2]), "=r"(r[3]) : "r"(addr));
}
__device__ __forceinline__ void mma_f16_16816(float* d, const uint32_t* a,
                                              uint32_t b0, uint32_t b1) {
    asm volatile(
        "mma.sync.aligned.m16n8k16.row.col.f32.f16.f16.f32 "
        "{%0,%1,%2,%3}, {%4,%5,%6,%7}, {%8,%9}, {%0,%1,%2,%3};"
        : "+f"(d[0]), "+f"(d[1]), "+f"(d[2]), "+f"(d[3])
        : "r"(a[0]), "r"(a[1]), "r"(a[2]), "r"(a[3]), "r"(b0), "r"(b1));
}
#define CP_ASYNC16(sa, gp) \
    asm volatile("cp.async.cg.shared.global [%0], [%1], 16;" :: "r"(sa), "l"(gp))
#define CP_COMMIT() asm volatile("cp.async.commit_group;")
#define CP_WAIT1()  asm volatile("cp.async.wait_group 1;")
#define CP_WAIT0()  asm volatile("cp.async.wait_group 0;")

// ---------------------------------------------------------------------------
// Scratch (allocation-free rule: device globals)
// ---------------------------------------------------------------------------
__device__ __align__(256) __half g_q16[M_TOT * DMODEL];   // Q fp16
__device__ __align__(256) __half g_k16[M_TOT * DMODEL];   // K fp16
__device__ __align__(256) __half g_v16[M_TOT * DMODEL];   // V fp16
__device__ __align__(256) __half g_x16[M_TOT * DMODEL];   // x fp16 (later attn-out)
__device__ __align__(256) __half g_w16[4 * DMODEL * DMODEL];

// Neighbor-pool metadata (per group of GRP consecutive s)
#define GRP   4
#define NGRP  (S_LEN / GRP)          // 1024
#define MAXU  72
__device__ int     g_ucnt[NGRP];
__device__ int     g_pool[NGRP][MAXU];
__device__ uint8_t g_remap[NGRP][GRP * WNBR];

// ---------------------------------------------------------------------------
// Fused prep: convert x and the 4 weight matrices to fp16
// ---------------------------------------------------------------------------
#define NX4  (M_TOT * DMODEL / 4)            // 1048576
#define NW4  (DMODEL * DMODEL / 4)           // 65536

__global__ __launch_bounds__(256)
void prep_kernel(const float* __restrict__ x,
                 const float* __restrict__ w0, const float* __restrict__ w1,
                 const float* __restrict__ w2, const float* __restrict__ w3,
                 __half* __restrict__ x16, __half* __restrict__ w16)
{
    int i = blockIdx.x * blockDim.x + threadIdx.x;
    const float* src;
    __half* dst;
    int l;
    if (i < NX4) {
        src = x; dst = x16; l = i;
    } else {
        int j = i - NX4;
        int w = j >> 16;  l = j & (NW4 - 1);
        src = (w == 0) ? w0 : (w == 1) ? w1 : (w == 2) ? w2 : w3;
        dst = w16 + (size_t)w * DMODEL * DMODEL;
    }
    float4 v = ((const float4*)src)[l];
    ((__half2*)dst)[l * 2 + 0] = __floats2half2_rn(v.x, v.y);
    ((__half2*)dst)[l * 2 + 1] = __floats2half2_rn(v.z, v.w);
}

// ---------------------------------------------------------------------------
// Pool prep (GRP=4): per group, dedup the 128 neighbor indices.
// Writes pool list (first MAXU), count, and u8 remap (valid iff u <= MAXU).
// ---------------------------------------------------------------------------
__global__ __launch_bounds__(256)
void pool_prep(const int* __restrict__ nidx)
{
    __shared__ uint8_t flag[S_LEN];
    __shared__ uint8_t pos[S_LEN];
    __shared__ int wsum[8];

    const int g = blockIdx.x, t = threadIdx.x;
    const int lane = t & 31, wid = t >> 5;

#pragma unroll
    for (int i = 0; i < 4; i++) ((uint32_t*)flag)[t + i * 256] = 0;
    __syncthreads();

    int idx = -1;
    if (t < GRP * WNBR) {
        idx = nidx[(g * GRP + (t >> 5)) * WNBR + (t & 31)];
        flag[idx] = 1;           // benign write race (same value)
    }
    __syncthreads();

    const int base = t * 16;
    int cnt = 0;
#pragma unroll
    for (int i = 0; i < 16; i++) cnt += flag[base + i];
    int sc = cnt;
#pragma unroll
    for (int o = 1; o < 32; o <<= 1) {
        int v = __shfl_up_sync(0xffffffffu, sc, o);
        if (lane >= o) sc += v;
    }
    if (lane == 31) wsum[wid] = sc;
    __syncthreads();
    int wbase = 0;
    for (int i = 0; i < wid; i++) wbase += wsum[i];
    int slot = wbase + sc - cnt;             // exclusive prefix
#pragma unroll
    for (int i = 0; i < 16; i++) {
        if (flag[base + i]) {
            pos[base + i] = (uint8_t)slot;
            if (slot < MAXU) g_pool[g][slot] = base + i;
            slot++;
        }
    }
    __syncthreads();
    int u = 0;
#pragma unroll
    for (int i = 0; i < 8; i++) u += wsum[i];
    if (t == 0) g_ucnt[g] = u;
    if (t < GRP * WNBR && u <= MAXU) g_remap[g][t] = pos[idx];
}

// ---------------------------------------------------------------------------
// Pure fp16 HMMA GEMM (round-8 proven config): C = A * B^T, fp32 accum.
// ---------------------------------------------------------------------------
#define ASTRIDE 40
#define TILE_B  (128 * ASTRIDE * 2)   // 10240
#define BUF_B   (2 * TILE_B)          // 20480
#define NSTAGE  3
#define GEMM_SMEM (NSTAGE * BUF_B)    // 61440

template <int EPI>
__device__ __forceinline__
void gemm_core(const __half* __restrict__ A, const __half* __restrict__ B,
               float* __restrict__ C, __half* __restrict__ Q16,
               __half* __restrict__ K16, __half* __restrict__ V16)
{
    extern __shared__ char smc[];
    const uint32_t sbase = smem_to_u32(smc);
    const int t = threadIdx.x, lane = t & 31, wid = t >> 5;
    const int wm = wid & 1, wn = wid >> 1;
    const int m0 = blockIdx.y * 128;
    const int n0 = blockIdx.x * 128;

    float acc[4][4][4];
#pragma unroll
    for (int mi = 0; mi < 4; mi++)
#pragma unroll
        for (int ni = 0; ni < 4; ni++)
#pragma unroll
            for (int j = 0; j < 4; j++) acc[mi][ni][j] = 0.0f;

    const int e0row = t >> 2,         e0c = (t & 3) * 8;
    const int e1row = (t + 256) >> 2, e1c = ((t + 256) & 3) * 8;
    const uint32_t so0 = (uint32_t)(e0row * ASTRIDE + e0c) * 2;
    const uint32_t so1 = (uint32_t)(e1row * ASTRIDE + e1c) * 2;

#define LOAD_CHUNK(kc, buf) do { \
    uint32_t bb = sbase + (uint32_t)(buf) * BUF_B; \
    size_t ga0 = (size_t)(m0 + e0row) * DMODEL + (kc) + e0c; \
    size_t ga1 = (size_t)(m0 + e1row) * DMODEL + (kc) + e1c; \
    size_t gb0 = (size_t)(n0 + e0row) * DMODEL + (kc) + e0c; \
    size_t gb1 = (size_t)(n0 + e1row) * DMODEL + (kc) + e1c; \
    CP_ASYNC16(bb + so0,          A + ga0); \
    CP_ASYNC16(bb + so1,          A + ga1); \
    CP_ASYNC16(bb + TILE_B + so0, B + gb0); \
    CP_ASYNC16(bb + TILE_B + so1, B + gb1); \
} while (0)

    LOAD_CHUNK(0, 0);
    CP_COMMIT();
    LOAD_CHUNK(32, 1);
    CP_COMMIT();

    const int lrow = lane & 15;
    const int lcol = lane >> 4;

    for (int c = 0; c < 16; c++) {
        CP_WAIT1();
        __syncthreads();
        if (c < 14) LOAD_CHUNK((c + 2) * 32, (c + 2) % NSTAGE);
        CP_COMMIT();

        const uint32_t ab = sbase + (uint32_t)(c % NSTAGE) * BUF_B;
#pragma unroll
        for (int ks = 0; ks < 2; ks++) {
            uint32_t af[4][4], bf[2][4];
            const int kcol = ks * 2 + lcol;
#pragma unroll
            for (int mi = 0; mi < 4; mi++) {
                uint32_t ad = ab + (uint32_t)(((wm * 64 + mi * 16 + lrow) * ASTRIDE) + kcol * 8) * 2;
                ldsm_x4(af[mi], ad);
            }
#pragma unroll
            for (int nb = 0; nb < 2; nb++) {
                uint32_t bd = ab + TILE_B +
                              (uint32_t)(((wn * 32 + nb * 16 + lrow) * ASTRIDE) + kcol * 8) * 2;
                ldsm_x4(bf[nb], bd);
            }
#pragma unroll
            for (int mi = 0; mi < 4; mi++)
#pragma unroll
                for (int ni = 0; ni < 4; ni++) {
                    const int nb = ni >> 1, nl = ni & 1;
                    mma_f16_16816(acc[mi][ni], af[mi], bf[nb][nl], bf[nb][nl + 2]);
                }
        }
    }
#undef LOAD_CHUNK

    if (EPI == 0) {
#pragma unroll
        for (int mi = 0; mi < 4; mi++) {
            const int r0 = m0 + wm * 64 + mi * 16 + (lane >> 2);
#pragma unroll
            for (int ni = 0; ni < 4; ni++) {
                const int cc = n0 + wn * 32 + ni * 8 + (lane & 3) * 2;
                *(float2*)(C + (size_t)r0 * DMODEL + cc)       = make_float2(acc[mi][ni][0], acc[mi][ni][1]);
                *(float2*)(C + (size_t)(r0 + 8) * DMODEL + cc) = make_float2(acc[mi][ni][2], acc[mi][ni][3]);
            }
        }
    } else {
        __half* dst;
        int nb0;
        if (n0 < 512)       { dst = Q16; nb0 = n0; }
        else if (n0 < 1024) { dst = K16; nb0 = n0 - 512; }
        else                { dst = V16; nb0 = n0 - 1024; }
#pragma unroll
        for (int mi = 0; mi < 4; mi++) {
            const int r0 = m0 + wm * 64 + mi * 16 + (lane >> 2);
#pragma unroll
            for (int ni = 0; ni < 4; ni++) {
                const int cc = nb0 + wn * 32 + ni * 8 + (lane & 3) * 2;
                *(__half2*)(dst + (size_t)r0 * DMODEL + cc) =
                    __floats2half2_rn(acc[mi][ni][0], acc[mi][ni][1]);
                *(__half2*)(dst + (size_t)(r0 + 8) * DMODEL + cc) =
                    __floats2half2_rn(acc[mi][ni][2], acc[mi][ni][3]);
            }
        }
    }
}

__global__ __launch_bounds__(256, 2)
void gemm_qkv(const __half* __restrict__ A, const __half* __restrict__ B,
              __half* __restrict__ Q16, __half* __restrict__ K16, __half* __restrict__ V16)
{
    gemm_core<1>(A, B, nullptr, Q16, K16, V16);
}

__global__ __launch_bounds__(256, 2)
void gemm_out(const __half* __restrict__ A, const __half* __restrict__ B,
              float* __restrict__ C)
{
    gemm_core<0>(A, B, C, nullptr, nullptr, nullptr);
}

// ---------------------------------------------------------------------------
// Pooled-K neighbor attention. One CTA per (group of 4 s, batch); warp = head.
// If u <= MAXU: stage union K rows ONCE, MMA scores for all 4 queries via
// remapped ldsm row addresses; PV stays direct-L2 gather per query (no V
// re-stage, no extra barriers). Else: per-query K staging (round-13 behavior).
// ---------------------------------------------------------------------------
#define ATTP_SMEM (MAXU * 1040)              // 74880 B

__global__ __launch_bounds__(256, 3)
void attn_kernel(const __half* __restrict__ q16,
                 const __half* __restrict__ k16,
                 const __half* __restrict__ v16,
                 const int*   __restrict__ nidx,
                 __half* __restrict__ a16)
{
    extern __shared__ char smc[];
    const uint32_t sbase = smem_to_u32(smc);
    __shared__ int     spool[MAXU];
    __shared__ int     sj[GRP][WNBR];
    __shared__ uint8_t rm[GRP * WNBR];
    __shared__ __half  sq[GRP * DMODEL];     // 4 KB

    const int g = blockIdx.x, b = blockIdx.y;
    const int s0 = g * GRP;
    const int t = threadIdx.x, h = t >> 5, lane = t & 31;
    const int u = g_ucnt[g];

    if (t < GRP * WNBR) {
        sj[t >> 5][t & 31] = nidx[(s0 + (t >> 5)) * WNBR + (t & 31)];
        rm[t] = g_remap[g][t];
    }
    if (t < MAXU) spool[t] = g_pool[g][t];
#pragma unroll
    for (int i = 0; i < GRP; i++)
        *(__half2*)(sq + i * DMODEL + t * 2) =
            *(const __half2*)(q16 + (size_t)(b * S_LEN + s0 + i) * DMODEL + t * 2);
    __syncthreads();

    if (u <= MAXU) {
        // ---- stage union K rows once ----
        const int nch = u * 64;
        for (int e = t; e < nch; e += 256) {
            int w = e >> 6, c = e & 63;
            CP_ASYNC16(sbase + (uint32_t)(w * 1040 + c * 16),
                       k16 + (size_t)(b * S_LEN + spool[w]) * DMODEL + c * 8);
        }
        CP_COMMIT();
        CP_WAIT0();
        __syncthreads();

        // ---- scores for all 4 queries (MMA, remapped rows) ----
        float svq[GRP][4];
#pragma unroll
        for (int q = 0; q < GRP; q++) {
            const int r0 = rm[q * 32 + (lane & 15)];
            const int r1 = rm[q * 32 + 16 + (lane & 15)];
            const uint32_t ad0 = sbase + (uint32_t)(r0 * 1040 + h * 128 + (lane >> 4) * 16);
            const uint32_t ad1 = sbase + (uint32_t)(r1 * 1040 + h * 128 + (lane >> 4) * 16);
            float acc0[4] = {0, 0, 0, 0}, acc1[4] = {0, 0, 0, 0};
#pragma unroll
            for (int kc = 0; kc < 4; kc++) {
                uint32_t b0 = *(const uint32_t*)(sq + q * DMODEL + h * 64 + kc * 16 + 2 * (lane & 3));
                uint32_t b1 = *(const uint32_t*)(sq + q * DMODEL + h * 64 + kc * 16 + 8 + 2 * (lane & 3));
                uint32_t a[4];
                ldsm_x4(a, ad0 + kc * 32);
                mma_f16_16816(acc0, a, b0, b1);
                ldsm_x4(a, ad1 + kc * 32);
                mma_f16_16816(acc1, a, b0, b1);
            }
            svq[q][0] = acc0[0] * 0.125f;  svq[q][1] = acc0[2] * 0.125f;
            svq[q][2] = acc1[0] * 0.125f;  svq[q][3] = acc1[2] * 0.125f;
        }

        // ---- softmax + PV (direct L2 gather) per query ----
#pragma unroll
        for (int q = 0; q < GRP; q++) {
            float m = fmaxf(fmaxf(svq[q][0], svq[q][1]), fmaxf(svq[q][2], svq[q][3]));
#pragma unroll
            for (int o = 4; o <= 16; o <<= 1) m = fmaxf(m, __shfl_xor_sync(0xffffffffu, m, o));
            float p[4], ssum = 0.0f;
#pragma unroll
            for (int j = 0; j < 4; j++) { p[j] = __expf(svq[q][j] - m); ssum += p[j]; }
#pragma unroll
            for (int o = 4; o <= 16; o <<= 1) ssum += __shfl_xor_sync(0xffffffffu, ssum, o);
            const float inv = 1.0f / ssum;
#pragma unroll
            for (int j = 0; j < 4; j++) p[j] *= inv;

            const int sjv = sj[q][lane];
            float ox = 0.0f, oy = 0.0f;
            const __half* vbase = v16 + (size_t)b * S_LEN * DMODEL + h * DHEAD + lane * 2;
#pragma unroll
            for (int w0 = 0; w0 < WNBR; w0 += 8) {
                float2 vv[8];
#pragma unroll
                for (int uu = 0; uu < 8; uu++) {
                    int row = __shfl_sync(0xffffffffu, sjv, w0 + uu);
                    vv[uu] = __half22float2(*(const __half2*)(vbase + (size_t)row * DMODEL));
                }
                const int j = w0 >> 3;
#pragma unroll
                for (int uu = 0; uu < 8; uu++) {
                    float pw = __shfl_sync(0xffffffffu, p[j], uu * 4);
                    ox += pw * vv[uu].x;
                    oy += pw * vv[uu].y;
                }
            }
            const size_t oidx = (size_t)(b * S_LEN + s0 + q) * DMODEL + h * DHEAD + lane * 2;
            *(__half2*)(a16 + oidx) = __floats2half2_rn(ox, oy);
        }
    } else {
        // ---- fallback: per-query K staging (round-13 behavior) ----
        for (int q = 0; q < GRP; q++) {
#pragma unroll
            for (int i = 0; i < 8; i++) {
                int e = t + i * 256, w = e >> 6, c = e & 63;
                CP_ASYNC16(sbase + (uint32_t)(w * 1040 + c * 16),
                           k16 + (size_t)(b * S_LEN + sj[q][w]) * DMODEL + c * 8);
            }
            CP_COMMIT();
            CP_WAIT0();
            __syncthreads();

            float acc0[4] = {0, 0, 0, 0}, acc1[4] = {0, 0, 0, 0};
            const uint32_t ad0 = sbase + (uint32_t)(((lane & 15)) * 1040 + h * 128 + (lane >> 4) * 16);
            const uint32_t ad1 = sbase + (uint32_t)((16 + (lane & 15)) * 1040 + h * 128 + (lane >> 4) * 16);
#pragma unroll
            for (int kc = 0; kc < 4; kc++) {
                uint32_t b0 = *(const uint32_t*)(sq + q * DMODEL + h * 64 + kc * 16 + 2 * (lane & 3));
                uint32_t b1 = *(const uint32_t*)(sq + q * DMODEL + h * 64 + kc * 16 + 8 + 2 * (lane & 3));
                uint32_t a[4];
                ldsm_x4(a, ad0 + kc * 32);
                mma_f16_16816(acc0, a, b0, b1);
                ldsm_x4(a, ad1 + kc * 32);
                mma_f16_16816(acc1, a, b0, b1);
            }
            float sv[4] = { acc0[0] * 0.125f, acc0[2] * 0.125f,
                            acc1[0] * 0.125f, acc1[2] * 0.125f };

            float m = fmaxf(fmaxf(sv[0], sv[1]), fmaxf(sv[2], sv[3]));
#pragma unroll
            for (int o = 4; o <= 16; o <<= 1) m = fmaxf(m, __shfl_xor_sync(0xffffffffu, m, o));
            float p[4], ssum = 0.0f;
#pragma unroll
            for (int j = 0; j < 4; j++) { p[j] = __expf(sv[j] - m); ssum += p[j]; }
#pragma unroll
            for (int o = 4; o <= 16; o <<= 1) ssum += __shfl_xor_sync(0xffffffffu, ssum, o);
            const float inv = 1.0f / ssum;
#pragma unroll
            for (int j = 0; j < 4; j++) p[j] *= inv;

            const int sjv = sj[q][lane];
            float ox = 0.0f, oy = 0.0f;
            const __half* vbase = v16 + (size_t)b * S_LEN * DMODEL + h * DHEAD + lane * 2;
#pragma unroll
            for (int w0 = 0; w0 < WNBR; w0 += 8) {
                float2 vv[8];
#pragma unroll
                for (int uu = 0; uu < 8; uu++) {
                    int row = __shfl_sync(0xffffffffu, sjv, w0 + uu);
                    vv[uu] = __half22float2(*(const __half2*)(vbase + (size_t)row * DMODEL));
                }
                const int j = w0 >> 3;
#pragma unroll
                for (int uu = 0; uu < 8; uu++) {
                    float pw = __shfl_sync(0xffffffffu, p[j], uu * 4);
                    ox += pw * vv[uu].x;
                    oy += pw * vv[uu].y;
                }
            }
            const size_t oidx = (size_t)(b * S_LEN + s0 + q) * DMODEL + h * DHEAD + lane * 2;
            *(__half2*)(a16 + oidx) = __floats2half2_rn(ox, oy);
            __syncthreads();             // before next query's restage
        }
    }
}

// ---------------------------------------------------------------------------
extern "C" void kernel_launch(void* const* d_in, const int* in_sizes, int n_in,
                              void* d_out, int out_size)
{
    const float* x    = (const float*)d_in[0];
    const float* Wq   = (const float*)d_in[1];
    const float* Wk   = (const float*)d_in[2];
    const float* Wv   = (const float*)d_in[3];
    const float* Wo   = (const float*)d_in[4];
    const int*   nidx = (const int*)  d_in[5];
    float*       out  = (float*)d_out;

    __half *q16, *k16, *v16, *x16, *w16;
    cudaGetSymbolAddress((void**)&q16, g_q16);
    cudaGetSymbolAddress((void**)&k16, g_k16);
    cudaGetSymbolAddress((void**)&v16, g_v16);
    cudaGetSymbolAddress((void**)&x16, g_x16);
    cudaGetSymbolAddress((void**)&w16, g_w16);

    static int attr_set = 0;
    if (!attr_set) {
        cudaFuncSetAttribute(attn_kernel, cudaFuncAttributeMaxDynamicSharedMemorySize, ATTP_SMEM);
        cudaFuncSetAttribute(gemm_qkv,    cudaFuncAttributeMaxDynamicSharedMemorySize, GEMM_SMEM);
        cudaFuncSetAttribute(gemm_out,    cudaFuncAttributeMaxDynamicSharedMemorySize, GEMM_SMEM);
        attr_set = 1;
    }

    const int NW = DMODEL * DMODEL;           // 262144

    prep_kernel<<<(NX4 + 4 * NW4) / 256, 256>>>(x, Wq, Wk, Wv, Wo, x16, w16);
    pool_prep<<<NGRP, 256>>>(nidx);

    dim3 qkvgrid(3 * DMODEL / 128, M_TOT / 128);   // (12, 64)
    gemm_qkv<<<qkvgrid, 256, GEMM_SMEM>>>(x16, w16, q16, k16, v16);

    dim3 agrid(NGRP, BATCH);                       // (1024, 2)
    attn_kernel<<<agrid, 256, ATTP_SMEM>>>(q16, k16, v16, nidx, x16);

    dim3 ogrid(DMODEL / 128, M_TOT / 128);         // (4, 64)
    gemm_out<<<ogrid, 256, GEMM_SMEM>>>(x16, w16 + 3 * NW, out);
}

// round 16
// speedup vs baseline: 1.1455x; 1.1455x over previous
#include <cuda_runtime.h>
#include <cuda_fp16.h>
#include <cstdint>

// Problem constants
#define BATCH   2
#define S_LEN   4096
#define DMODEL  512
#define NHEAD   8
#define DHEAD   64
#define WNBR    32
#define M_TOT   (BATCH * S_LEN)      // 8192

// ---------------------------------------------------------------------------
// PTX helpers — base sm_103 only (NO tcgen05)
// ---------------------------------------------------------------------------
__device__ __forceinline__ uint32_t smem_to_u32(const void* p) {
    uint32_t a;
    asm("{ .reg .u64 t; cvta.to.shared.u64 t, %1; cvt.u32.u64 %0, t; }" : "=r"(a) : "l"(p));
    return a;
}
__device__ __forceinline__ void ldsm_x4(uint32_t* r, uint32_t addr) {
    asm volatile("ldmatrix.sync.aligned.m8n8.x4.shared.b16 {%0,%1,%2,%3}, [%4];"
                 : "=r"(r[0]), "=r"(r[1]), "=r"(r[2]), "=r"(r[3]) : "r"(addr));
}
__device__ __forceinline__ void mma_f16_16816(float* d, const uint32_t* a,
                                              uint32_t b0, uint32_t b1) {
    asm volatile(
        "mma.sync.aligned.m16n8k16.row.col.f32.f16.f16.f32 "
        "{%0,%1,%2,%3}, {%4,%5,%6,%7}, {%8,%9}, {%0,%1,%2,%3};"
        : "+f"(d[0]), "+f"(d[1]), "+f"(d[2]), "+f"(d[3])
        : "r"(a[0]), "r"(a[1]), "r"(a[2]), "r"(a[3]), "r"(b0), "r"(b1));
}
#define CP_ASYNC16(sa, gp) \
    asm volatile("cp.async.cg.shared.global [%0], [%1], 16;" :: "r"(sa), "l"(gp))
#define CP_COMMIT() asm volatile("cp.async.commit_group;")
#define CP_WAIT1()  asm volatile("cp.async.wait_group 1;")
#define CP_WAIT0()  asm volatile("cp.async.wait_group 0;")

// ---------------------------------------------------------------------------
// Scratch (allocation-free rule: device globals)
// ---------------------------------------------------------------------------
__device__ __align__(256) __half g_q16[M_TOT * DMODEL];   // Q fp16
__device__ __align__(256) __half g_k16[M_TOT * DMODEL];   // K fp16
__device__ __align__(256) __half g_v16[M_TOT * DMODEL];   // V fp16
__device__ __align__(256) __half g_x16[M_TOT * DMODEL];   // x fp16 (later attn-out)
__device__ __align__(256) __half g_w16[4 * DMODEL * DMODEL];

// ---------------------------------------------------------------------------
// Fused prep: convert x and the 4 weight matrices to fp16
// ---------------------------------------------------------------------------
#define NX4  (M_TOT * DMODEL / 4)            // 1048576
#define NW4  (DMODEL * DMODEL / 4)           // 65536

__global__ __launch_bounds__(256)
void prep_kernel(const float* __restrict__ x,
                 const float* __restrict__ w0, const float* __restrict__ w1,
                 const float* __restrict__ w2, const float* __restrict__ w3,
                 __half* __restrict__ x16, __half* __restrict__ w16)
{
    int i = blockIdx.x * blockDim.x + threadIdx.x;
    const float* src;
    __half* dst;
    int l;
    if (i < NX4) {
        src = x; dst = x16; l = i;
    } else {
        int j = i - NX4;
        int w = j >> 16;  l = j & (NW4 - 1);
        src = (w == 0) ? w0 : (w == 1) ? w1 : (w == 2) ? w2 : w3;
        dst = w16 + (size_t)w * DMODEL * DMODEL;
    }
    float4 v = ((const float4*)src)[l];
    ((__half2*)dst)[l * 2 + 0] = __floats2half2_rn(v.x, v.y);
    ((__half2*)dst)[l * 2 + 1] = __floats2half2_rn(v.z, v.w);
}

// ---------------------------------------------------------------------------
// Pure fp16 HMMA GEMM, 16-warp variant: C = A * B^T, fp32 accum.
// CTA 128x128, BK=32, 512 threads (16 warps), warp grid 4(M) x 4(N),
// warp tile 32x32 -> 8 warps/SMSP at 2 CTAs/SM for latency hiding.
// 3-stage cp.async pipeline, one __syncthreads per K-chunk.
// EPI: 0 = fp32 C ; 1 = QKV fp16 (q / k / v selected by n0 block)
// ---------------------------------------------------------------------------
#define ASTRIDE 40
#define TILE_B  (128 * ASTRIDE * 2)   // 10240
#define BUF_B   (2 * TILE_B)          // 20480
#define NSTAGE  3
#define GEMM_SMEM (NSTAGE * BUF_B)    // 61440

template <int EPI>
__device__ __forceinline__
void gemm_core(const __half* __restrict__ A, const __half* __restrict__ B,
               float* __restrict__ C, __half* __restrict__ Q16,
               __half* __restrict__ K16, __half* __restrict__ V16)
{
    extern __shared__ char smc[];
    const uint32_t sbase = smem_to_u32(smc);
    const int t = threadIdx.x, lane = t & 31, wid = t >> 5;
    const int wm = wid & 3, wn = wid >> 2;
    const int m0 = blockIdx.y * 128;
    const int n0 = blockIdx.x * 128;

    float acc[2][4][4];
#pragma unroll
    for (int mi = 0; mi < 2; mi++)
#pragma unroll
        for (int ni = 0; ni < 4; ni++)
#pragma unroll
            for (int j = 0; j < 4; j++) acc[mi][ni][j] = 0.0f;

    // 512 threads: 1 A-chunk + 1 B-chunk (16B) per thread per K-chunk
    const int erow = t >> 2;            // 0..127
    const int ec   = (t & 3) * 8;       // halves
    const uint32_t so = (uint32_t)(erow * ASTRIDE + ec) * 2;

#define LOAD_CHUNK(kc, buf) do { \
    uint32_t bb = sbase + (uint32_t)(buf) * BUF_B; \
    CP_ASYNC16(bb + so,          A + (size_t)(m0 + erow) * DMODEL + (kc) + ec); \
    CP_ASYNC16(bb + TILE_B + so, B + (size_t)(n0 + erow) * DMODEL + (kc) + ec); \
} while (0)

    LOAD_CHUNK(0, 0);
    CP_COMMIT();
    LOAD_CHUNK(32, 1);
    CP_COMMIT();

    const int lrow = lane & 15;
    const int lcol = lane >> 4;

    for (int c = 0; c < 16; c++) {
        CP_WAIT1();                    // chunk c resident
        __syncthreads();               // buf (c+2)%3 free
        if (c < 14) LOAD_CHUNK((c + 2) * 32, (c + 2) % NSTAGE);
        CP_COMMIT();

        const uint32_t ab = sbase + (uint32_t)(c % NSTAGE) * BUF_B;
#pragma unroll
        for (int ks = 0; ks < 2; ks++) {
            uint32_t af[2][4], bf[2][4];
            const int kcol = ks * 2 + lcol;
#pragma unroll
            for (int mi = 0; mi < 2; mi++) {
                uint32_t ad = ab + (uint32_t)(((wm * 32 + mi * 16 + lrow) * ASTRIDE) + kcol * 8) * 2;
                ldsm_x4(af[mi], ad);
            }
#pragma unroll
            for (int nb = 0; nb < 2; nb++) {
                uint32_t bd = ab + TILE_B +
                              (uint32_t)(((wn * 32 + nb * 16 + lrow) * ASTRIDE) + kcol * 8) * 2;
                ldsm_x4(bf[nb], bd);
            }
#pragma unroll
            for (int mi = 0; mi < 2; mi++)
#pragma unroll
                for (int ni = 0; ni < 4; ni++) {
                    const int nb = ni >> 1, nl = ni & 1;
                    mma_f16_16816(acc[mi][ni], af[mi], bf[nb][nl], bf[nb][nl + 2]);
                }
        }
    }
#undef LOAD_CHUNK

    if (EPI == 0) {
#pragma unroll
        for (int mi = 0; mi < 2; mi++) {
            const int r0 = m0 + wm * 32 + mi * 16 + (lane >> 2);
#pragma unroll
            for (int ni = 0; ni < 4; ni++) {
                const int cc = n0 + wn * 32 + ni * 8 + (lane & 3) * 2;
                *(float2*)(C + (size_t)r0 * DMODEL + cc)       = make_float2(acc[mi][ni][0], acc[mi][ni][1]);
                *(float2*)(C + (size_t)(r0 + 8) * DMODEL + cc) = make_float2(acc[mi][ni][2], acc[mi][ni][3]);
            }
        }
    } else {
        __half* dst;
        int nb0;
        if (n0 < 512)       { dst = Q16; nb0 = n0; }
        else if (n0 < 1024) { dst = K16; nb0 = n0 - 512; }
        else                { dst = V16; nb0 = n0 - 1024; }
#pragma unroll
        for (int mi = 0; mi < 2; mi++) {
            const int r0 = m0 + wm * 32 + mi * 16 + (lane >> 2);
#pragma unroll
            for (int ni = 0; ni < 4; ni++) {
                const int cc = nb0 + wn * 32 + ni * 8 + (lane & 3) * 2;
                *(__half2*)(dst + (size_t)r0 * DMODEL + cc) =
                    __floats2half2_rn(acc[mi][ni][0], acc[mi][ni][1]);
                *(__half2*)(dst + (size_t)(r0 + 8) * DMODEL + cc) =
                    __floats2half2_rn(acc[mi][ni][2], acc[mi][ni][3]);
            }
        }
    }
}

__global__ __launch_bounds__(512, 2)
void gemm_qkv(const __half* __restrict__ A, const __half* __restrict__ B,
              __half* __restrict__ Q16, __half* __restrict__ K16, __half* __restrict__ V16)
{
    gemm_core<1>(A, B, nullptr, Q16, K16, V16);
}

__global__ __launch_bounds__(512, 2)
void gemm_out(const __half* __restrict__ A, const __half* __restrict__ B,
              float* __restrict__ C)
{
    gemm_core<0>(A, B, C, nullptr, nullptr, nullptr);
}

// ---------------------------------------------------------------------------
// Neighbor attention with HMMA scores (round-13 proven best, unchanged).
// One CTA per (b,s); warp = head. K staged in smem (pitch 1040B), scores via
// mma.m16n8k16 with q replicated across N-cols, softmax via shfl butterfly,
// PV via direct-L2 gather. Output fp16.
// ---------------------------------------------------------------------------
#define ATT_SMEM (WNBR * 1040)               // 33280 B

__global__ __launch_bounds__(256, 6)
void attn_kernel(const __half* __restrict__ q16,
                 const __half* __restrict__ k16,
                 const __half* __restrict__ v16,
                 const int*   __restrict__ nidx,
                 __half* __restrict__ a16)
{
    extern __shared__ char smc[];
    const uint32_t sbase = smem_to_u32(smc);
    __shared__ int    sj[WNBR];
    __shared__ __half sq16[DMODEL];

    const int bs   = blockIdx.x;
    const int s    = bs & (S_LEN - 1);
    const int b    = bs >> 12;
    const int t    = threadIdx.x;
    const int h    = t >> 5;
    const int lane = t & 31;

    if (t < WNBR) sj[t] = nidx[s * WNBR + t];
    *(__half2*)(sq16 + t * 2) = *(const __half2*)(q16 + (size_t)bs * DMODEL + t * 2);
    __syncthreads();

    // Stage K rows: 32 rows x 1024 B, 64 16B-chunks per row, 8 per thread.
#pragma unroll
    for (int i = 0; i < 8; i++) {
        int e = t + i * 256;
        int w = e >> 6, c = e & 63;
        size_t src = (size_t)(b * S_LEN + sj[w]) * DMODEL + c * 8;
        CP_ASYNC16(sbase + (uint32_t)(w * 1040 + c * 16), k16 + src);
    }
    CP_COMMIT();
    CP_WAIT0();
    __syncthreads();

    // Scores via HMMA
    float acc_s[2][4];
#pragma unroll
    for (int mt = 0; mt < 2; mt++)
#pragma unroll
        for (int j = 0; j < 4; j++) acc_s[mt][j] = 0.0f;

#pragma unroll
    for (int kc = 0; kc < 4; kc++) {
        uint32_t b0 = *(const uint32_t*)(sq16 + h * 64 + kc * 16 + 2 * (lane & 3));
        uint32_t b1 = *(const uint32_t*)(sq16 + h * 64 + kc * 16 + 8 + 2 * (lane & 3));
#pragma unroll
        for (int mt = 0; mt < 2; mt++) {
            uint32_t a[4];
            uint32_t ad = sbase + (uint32_t)((mt * 16 + (lane & 15)) * 1040
                                             + h * 128 + kc * 32 + (lane >> 4) * 16);
            ldsm_x4(a, ad);
            mma_f16_16816(acc_s[mt], a, b0, b1);
        }
    }

    float sv[4] = { acc_s[0][0] * 0.125f, acc_s[0][2] * 0.125f,
                    acc_s[1][0] * 0.125f, acc_s[1][2] * 0.125f };

    // Softmax across 32 neighbors
    float m = fmaxf(fmaxf(sv[0], sv[1]), fmaxf(sv[2], sv[3]));
#pragma unroll
    for (int o = 4; o <= 16; o <<= 1) m = fmaxf(m, __shfl_xor_sync(0xffffffffu, m, o));
    float p[4], ssum = 0.0f;
#pragma unroll
    for (int j = 0; j < 4; j++) { p[j] = __expf(sv[j] - m); ssum += p[j]; }
#pragma unroll
    for (int o = 4; o <= 16; o <<= 1) ssum += __shfl_xor_sync(0xffffffffu, ssum, o);
    const float inv = 1.0f / ssum;
#pragma unroll
    for (int j = 0; j < 4; j++) p[j] *= inv;

    // PV: direct L2 gather, 8-deep batches
    float ox = 0.0f, oy = 0.0f;
    const __half* vbase = v16 + (size_t)b * S_LEN * DMODEL + h * DHEAD + lane * 2;
#pragma unroll
    for (int w0 = 0; w0 < WNBR; w0 += 8) {
        float2 vv[8];
#pragma unroll
        for (int u = 0; u < 8; u++)
            vv[u] = __half22float2(*(const __half2*)(vbase + (size_t)sj[w0 + u] * DMODEL));
        const int j = w0 >> 3;
#pragma unroll
        for (int u = 0; u < 8; u++) {
            float pw = __shfl_sync(0xffffffffu, p[j], u * 4);
            ox += pw * vv[u].x;
            oy += pw * vv[u].y;
        }
    }

    const size_t oidx = (size_t)bs * DMODEL + h * DHEAD + lane * 2;
    *(__half2*)(a16 + oidx) = __floats2half2_rn(ox, oy);
}

// ---------------------------------------------------------------------------
extern "C" void kernel_launch(void* const* d_in, const int* in_sizes, int n_in,
                              void* d_out, int out_size)
{
    const float* x    = (const float*)d_in[0];
    const float* Wq   = (const float*)d_in[1];
    const float* Wk   = (const float*)d_in[2];
    const float* Wv   = (const float*)d_in[3];
    const float* Wo   = (const float*)d_in[4];
    const int*   nidx = (const int*)  d_in[5];
    float*       out  = (float*)d_out;

    __half *q16, *k16, *v16, *x16, *w16;
    cudaGetSymbolAddress((void**)&q16, g_q16);
    cudaGetSymbolAddress((void**)&k16, g_k16);
    cudaGetSymbolAddress((void**)&v16, g_v16);
    cudaGetSymbolAddress((void**)&x16, g_x16);
    cudaGetSymbolAddress((void**)&w16, g_w16);

    static int attr_set = 0;
    if (!attr_set) {
        cudaFuncSetAttribute(attn_kernel, cudaFuncAttributeMaxDynamicSharedMemorySize, ATT_SMEM);
        cudaFuncSetAttribute(gemm_qkv,    cudaFuncAttributeMaxDynamicSharedMemorySize, GEMM_SMEM);
        cudaFuncSetAttribute(gemm_out,    cudaFuncAttributeMaxDynamicSharedMemorySize, GEMM_SMEM);
        attr_set = 1;
    }

    const int NW = DMODEL * DMODEL;           // 262144

    prep_kernel<<<(NX4 + 4 * NW4) / 256, 256>>>(x, Wq, Wk, Wv, Wo, x16, w16);

    dim3 qkvgrid(3 * DMODEL / 128, M_TOT / 128);   // (12, 64) = 768 CTAs
    gemm_qkv<<<qkvgrid, 512, GEMM_SMEM>>>(x16, w16, q16, k16, v16);

    attn_kernel<<<M_TOT, 256, ATT_SMEM>>>(q16, k16, v16, nidx, x16);

    dim3 ogrid(DMODEL / 128, M_TOT / 128);         // (4, 64) = 256 CTAs
    gemm_out<<<ogrid, 512, GEMM_SMEM>>>(x16, w16 + 3 * NW, out);
}